// round 13
// baseline (speedup 1.0000x reference)
#include <cuda_runtime.h>
#include <cuda_bf16.h>
#include <cuda_fp16.h>

// ---------------------------------------------------------------------------
// Turbo decoder (linear-domain BCJR in log2 units), 8-state RSC,
// B=256, K=6144, 6 iterations. Sliding-window (L=16, W=16), 384 chunks.
// PERSISTENT kernel: 1536 blocks (guaranteed co-resident at 12 blocks/SM),
// each processes 2 chunk-units per pass; 12 passes separated by a software
// grid barrier. L1 stays warm across passes (no launch-boundary flush).
// Branch metrics pre-combined: G[t][b] = (g0', g1') float2; passes write the
// next pass's G directly through the interleaver via SD = (ls'+lp', ls'-lp').
// ---------------------------------------------------------------------------

constexpr int Kc = 6144;
constexpr int Bc = 256;
constexpr int Lc = 16;
constexpr int Wc = 16;
constexpr int Cc = Kc / Lc;           // 384 chunks
constexpr int Hc = Lc / 2;            // 8
constexpr int NB = 1536;              // persistent grid size (2 units/block/pass)
constexpr float SCALEF   = 0.7213475204444817f;   // 0.5*log2(e)
constexpr float OUTSCALE = -1.3862943611198906f;  // -2*ln2  (undo SCALEF, negate)
constexpr float GCLAMP   = 60.0f;                 // log2-unit branch clamp

// Static device scratch (no allocations anywhere).
__device__ float  g_ls1[Kc * Bc];
__device__ float  g_lp2[Kc * Bc];
__device__ float2 g_SD1[Kc * Bc];
__device__ float2 g_SD2[Kc * Bc];
__device__ float2 g_G1[Kc * Bc];
__device__ float2 g_G2[Kc * Bc];
__device__ float  g_lpost[Kc * Bc];
__device__ int    g_inv[Kc];
__device__ unsigned g_bar;

__device__ __forceinline__ float ex2f(float x) {
    float y; asm("ex2.approx.ftz.f32 %0, %1;" : "=f"(y) : "f"(x)); return y;
}
__device__ __forceinline__ float lg2f(float x) {
    float y; asm("lg2.approx.ftz.f32 %0, %1;" : "=f"(y) : "f"(x)); return y;
}

// r = 2^-(ilogb(s)) : exponent-field trick, no MUFU.
__device__ __forceinline__ float norm_scale(float s) {
    return __uint_as_float(0x7F000000u - (__float_as_uint(s) & 0x7F800000u));
}

__device__ __forceinline__ void weights(float2 g, float (&e)[4]) {
    e[0] = ex2f(g.x);  e[1] = ex2f(-g.x);
    e[2] = ex2f(g.y);  e[3] = ex2f(-g.y);
}

// Trellis (G0=(1,0,1,1), G1=(1,1,0,1), MU=3):
//   weight(s,u=0) = e0p for s in {0,1,6,7}, e1p for s in {2,3,4,5}; u=1 -> e*n.
//   next: 0:(0,4) 1:(4,0) 2:(5,1) 3:(1,5) 4:(2,6) 5:(6,2) 6:(7,3) 7:(3,7)

__device__ __forceinline__ void norm8(float (&v)[8]) {
    float s = ((v[0]+v[1])+(v[2]+v[3])) + ((v[4]+v[5])+(v[6]+v[7]));
    float r = norm_scale(s);
    #pragma unroll
    for (int i = 0; i < 8; ++i) v[i] *= r;
}

__device__ __forceinline__ void fwd_step(const float (&e)[4], float (&a)[8]) {
    float n0 = a[0]*e[0] + a[1]*e[1];
    float n4 = a[0]*e[1] + a[1]*e[0];
    float n5 = a[2]*e[2] + a[3]*e[3];
    float n1 = a[2]*e[3] + a[3]*e[2];
    float n2 = a[4]*e[2] + a[5]*e[3];
    float n6 = a[4]*e[3] + a[5]*e[2];
    float n7 = a[6]*e[0] + a[7]*e[1];
    float n3 = a[6]*e[1] + a[7]*e[0];
    a[0]=n0; a[1]=n1; a[2]=n2; a[3]=n3; a[4]=n4; a[5]=n5; a[6]=n6; a[7]=n7;
}

__device__ __forceinline__ void bwd_step(const float (&e)[4], float (&B)[8]) {
    float n0 = B[0]*e[0] + B[4]*e[1];
    float n1 = B[4]*e[0] + B[0]*e[1];
    float n2 = B[5]*e[2] + B[1]*e[3];
    float n3 = B[1]*e[2] + B[5]*e[3];
    float n4 = B[2]*e[2] + B[6]*e[3];
    float n5 = B[6]*e[2] + B[2]*e[3];
    float n6 = B[7]*e[0] + B[3]*e[1];
    float n7 = B[3]*e[0] + B[7]*e[1];
    B[0]=n0; B[1]=n1; B[2]=n2; B[3]=n3; B[4]=n4; B[5]=n5; B[6]=n6; B[7]=n7;
}

__device__ __forceinline__ uint4 pack8(const float (&v)[8]) {
    __half2 h01 = __floats2half2_rn(v[0], v[1]);
    __half2 h23 = __floats2half2_rn(v[2], v[3]);
    __half2 h45 = __floats2half2_rn(v[4], v[5]);
    __half2 h67 = __floats2half2_rn(v[6], v[7]);
    uint4 pk;
    pk.x = *reinterpret_cast<unsigned*>(&h01);
    pk.y = *reinterpret_cast<unsigned*>(&h23);
    pk.z = *reinterpret_cast<unsigned*>(&h45);
    pk.w = *reinterpret_cast<unsigned*>(&h67);
    return pk;
}

__device__ __forceinline__ void unpack8(uint4 pk, float (&v)[8]) {
    float2 q01 = __half22float2(*reinterpret_cast<__half2*>(&pk.x));
    float2 q23 = __half22float2(*reinterpret_cast<__half2*>(&pk.y));
    float2 q45 = __half22float2(*reinterpret_cast<__half2*>(&pk.z));
    float2 q67 = __half22float2(*reinterpret_cast<__half2*>(&pk.w));
    v[0]=q01.x; v[1]=q01.y; v[2]=q23.x; v[3]=q23.y;
    v[4]=q45.x; v[5]=q45.y; v[6]=q67.x; v[7]=q67.y;
}

__device__ __forceinline__ float posterior8(const float (&A)[8], const float (&v)[8],
                                            const float (&e)[4]) {
    float u0 = e[0] * (A[0]*v[0] + A[1]*v[4] + A[6]*v[7] + A[7]*v[3])
             + e[2] * (A[2]*v[5] + A[3]*v[1] + A[4]*v[2] + A[5]*v[6]);
    float u1 = e[1] * (A[0]*v[4] + A[1]*v[0] + A[6]*v[3] + A[7]*v[7])
             + e[3] * (A[2]*v[1] + A[3]*v[5] + A[4]*v[6] + A[5]*v[2]);
    return 0.5f * (lg2f(fmaxf(u0, 1e-30f)) - lg2f(fmaxf(u1, 1e-30f)));
}

// ---------------------------------------------------------------------------
// Setup kernels
// ---------------------------------------------------------------------------
__global__ void unpack_kernel(const float* __restrict__ in) {
    __shared__ float tile[3][32][33];
    int t0 = blockIdx.x * 32;
    int b0 = blockIdx.y * 32;
    int tid = threadIdx.x;
    for (int e = tid; e < 32 * 96; e += 256) {
        int db  = e / 96;
        int off = e % 96;
        float v = in[(size_t)(b0 + db) * (3 * Kc) + 3 * t0 + off];
        tile[off % 3][off / 3][db] = -SCALEF * v;
    }
    __syncthreads();
    for (int e = tid; e < 1024; e += 256) {
        int tt = e >> 5, bb = e & 31;
        int idx = (t0 + tt) * Bc + b0 + bb;
        float vls = tile[0][tt][bb];
        float vp1 = tile[1][tt][bb];
        float vp2 = tile[2][tt][bb];
        float s1 = vls + vp1, d1 = vls - vp1;
        g_ls1[idx] = vls;
        g_lp2[idx] = vp2;
        g_SD1[idx] = make_float2(s1, d1);
        g_G1[idx]  = make_float2(s1, d1);     // la = 0 for iteration 0
    }
}

__global__ void build_inv_kernel(const int* __restrict__ perm) {
    int j = blockIdx.x * 256 + threadIdx.x;
    if (j < Kc) g_inv[perm[j]] = j;
    if (j == 0) g_bar = 0;                    // reset persistent barrier
}

__global__ void gather2_kernel(const int* __restrict__ perm) {
    int b  = threadIdx.x;
    int j0 = blockIdx.x * 8;
    #pragma unroll
    for (int r = 0; r < 8; ++r) {
        int j = j0 + r;
        float vls = g_ls1[perm[j] * Bc + b];
        float vlp = g_lp2[j * Bc + b];
        g_SD2[j * Bc + b] = make_float2(vls + vlp, vls - vlp);
    }
}

// ---------------------------------------------------------------------------
// One chunk-unit of one BCJR pass (two-warp schedule; assumes __syncthreads
// in BOTH warps' paths).
// ---------------------------------------------------------------------------
__device__ __forceinline__ void do_chunk(
    int c, int b, int lane, int wid, int last,
    const float2* __restrict__ G, float2* __restrict__ Gout,
    const float2* __restrict__ SD, const int* __restrict__ map,
    uint4 (&sbeta)[Lc][32], uint4 (&salpha)[Hc][32])
{
    const int t_lo = c * Lc;
    const int t_sh = t_lo + Lc - 1;

    if (wid == 0) {
        // ================= backward warp =================
        float B[8];
        #pragma unroll
        for (int s = 0; s < 8; ++s) B[s] = 0.125f;

        int t_hi = t_sh + Wc;
        if (t_hi > Kc - 1) t_hi = Kc - 1;     // uniform init == exact beta_K
        for (int t = t_hi; t > t_sh; t -= 4) {
            float2 ga = G[(t    ) * Bc + b];
            float2 gb = G[(t - 1) * Bc + b];
            float2 gc2 = G[(t - 2) * Bc + b];
            float2 gd = G[(t - 3) * Bc + b];
            float e[4];
            weights(ga, e);  bwd_step(e, B);
            weights(gb, e);  bwd_step(e, B);
            norm8(B);
            weights(gc2, e); bwd_step(e, B);
            weights(gd, e);  bwd_step(e, B);
            norm8(B);
        }
        #pragma unroll
        for (int t2 = t_sh; t2 >= t_lo + Hc; --t2) {
            sbeta[t2 - t_lo][lane] = pack8(B);
            float e[4];
            weights(G[t2 * Bc + b], e);
            bwd_step(e, B);
            norm8(B);
        }
        __syncthreads();
        #pragma unroll
        for (int i = Hc - 1; i >= 0; --i) {
            sbeta[i][lane] = pack8(B);
            float e[4];
            weights(G[(t_lo + i) * Bc + b], e);
            bwd_step(e, B);
            norm8(B);
        }
        // posteriors for the LOWER half
        #pragma unroll
        for (int i = 0; i < Hc; ++i) {
            int t = t_lo + i;
            float2 g = G[t * Bc + b];
            float A[8], v[8], e[4];
            unpack8(salpha[i][lane], A);
            unpack8(sbeta[i][lane], v);
            weights(g, e);
            float lps = posterior8(A, v, e);
            int row = map[t];
            float2 sd = SD[row * Bc + b];
            float ext = lps - 0.5f * (g.x + g.y);
            Gout[row * Bc + b] = make_float2(
                fminf(fmaxf(sd.x + ext, -GCLAMP), GCLAMP),
                fminf(fmaxf(sd.y + ext, -GCLAMP), GCLAMP));
            if (last) g_lpost[t * Bc + b] = lps;
        }
    } else {
        // ================= forward warp =================
        float A[8];
        int t0 = t_lo - Wc; if (t0 < 0) t0 = 0;
        if (t0 == 0 && c == 0) {
            #pragma unroll
            for (int s = 0; s < 8; ++s) A[s] = 0.0f;
            A[0] = 1.0f;
        } else if (t0 == 0) {                 // c==1: warm from exact init
            A[0] = 1.0f;
            #pragma unroll
            for (int s = 1; s < 8; ++s) A[s] = 0.0f;
        } else {
            #pragma unroll
            for (int s = 0; s < 8; ++s) A[s] = 0.125f;
        }
        for (int t = t0; t < t_lo; t += 4) {
            float2 ga = G[(t    ) * Bc + b];
            float2 gb = G[(t + 1) * Bc + b];
            float2 gc2 = G[(t + 2) * Bc + b];
            float2 gd = G[(t + 3) * Bc + b];
            float e[4];
            weights(ga, e);  fwd_step(e, A);
            weights(gb, e);  fwd_step(e, A);
            norm8(A);
            weights(gc2, e); fwd_step(e, A);
            weights(gd, e);  fwd_step(e, A);
            norm8(A);
        }
        #pragma unroll
        for (int i = 0; i < Hc; ++i) {
            salpha[i][lane] = pack8(A);
            float e[4];
            weights(G[(t_lo + i) * Bc + b], e);
            fwd_step(e, A);
            norm8(A);
        }
        __syncthreads();
        #pragma unroll
        for (int t = t_lo + Hc; t <= t_sh; ++t) {
            float2 g = G[t * Bc + b];
            float e[4], v[8];
            weights(g, e);
            unpack8(sbeta[t - t_lo][lane], v);
            float lps = posterior8(A, v, e);
            int row = map[t];
            float2 sd = SD[row * Bc + b];
            float ext = lps - 0.5f * (g.x + g.y);
            Gout[row * Bc + b] = make_float2(
                fminf(fmaxf(sd.x + ext, -GCLAMP), GCLAMP),
                fminf(fmaxf(sd.y + ext, -GCLAMP), GCLAMP));
            if (last) g_lpost[t * Bc + b] = lps;
            fwd_step(e, A);
            norm8(A);
        }
    }
}

// ---------------------------------------------------------------------------
// Persistent kernel: 12 BCJR passes with software grid barriers.
// 1536 blocks, 12/SM guaranteed resident (regs<=85 via launch_bounds,
// smem 12.3KB) -> capacity >= 1776 blocks on 148 SMs; no deadlock.
// ---------------------------------------------------------------------------
__global__ void __launch_bounds__(64, 12) turbo_persist(const int* __restrict__ perm) {
    __shared__ uint4 sbeta[Lc][32];    // 8 KB
    __shared__ uint4 salpha[Hc][32];   // 4 KB

    const int lane = threadIdx.x & 31;
    const int wid  = threadIdx.x >> 5;

    for (int pass = 0; pass < 12; ++pass) {
        const int dec  = pass & 1;
        const int last = (pass == 11);
        const float2* __restrict__ G  = dec ? g_G2 : g_G1;
        float2* __restrict__ Gout     = dec ? g_G1 : g_G2;
        const float2* __restrict__ SD = dec ? g_SD1 : g_SD2;
        const int* __restrict__ map   = dec ? perm : g_inv;

        #pragma unroll 1
        for (int half = 0; half < 2; ++half) {
            int unit = blockIdx.x + half * NB;      // 0..3071
            int c    = unit >> 3;                   // chunk index
            int b    = (unit & 7) * 32 + lane;      // batch element
            do_chunk(c, b, lane, wid, last, G, Gout, SD, map, sbeta, salpha);
            __syncthreads();                        // smem reuse across units
        }

        // ---- software grid barrier ----
        if (threadIdx.x == 0) {
            __threadfence();                        // release our G writes
            atomicAdd(&g_bar, 1u);
            unsigned target = (unsigned)(pass + 1) * NB;
            while (*((volatile unsigned*)&g_bar) < target) __nanosleep(128);
            __threadfence();                        // acquire others' writes
        }
        __syncthreads();
    }
}

// ---------------------------------------------------------------------------
// Output: out[b][i] = -2*ln2 * lpost'[inv[i]][b]
// ---------------------------------------------------------------------------
__global__ void output_kernel(float* __restrict__ out) {
    __shared__ float tile[32][33];
    int i0 = blockIdx.x * 32, b0 = blockIdx.y * 32;
    int tid = threadIdx.x;
    for (int e = tid; e < 1024; e += 256) {
        int ii = e >> 5, bb = e & 31;
        tile[ii][bb] = OUTSCALE * g_lpost[g_inv[i0 + ii] * Bc + b0 + bb];
    }
    __syncthreads();
    for (int e = tid; e < 1024; e += 256) {
        int bb = e >> 5, ii = e & 31;
        out[(size_t)(b0 + bb) * Kc + i0 + ii] = tile[ii][bb];
    }
}

// ---------------------------------------------------------------------------
extern "C" void kernel_launch(void* const* d_in, const int* in_sizes, int n_in,
                              void* d_out, int out_size) {
    const float* in  = (const float*)d_in[0];
    const int* perm  = (const int*)d_in[1];
    float* out       = (float*)d_out;

    dim3 upg(Kc / 32, Bc / 32);
    unpack_kernel<<<upg, 256>>>(in);
    build_inv_kernel<<<Kc / 256, 256>>>(perm);   // also resets g_bar
    gather2_kernel<<<Kc / 8, 256>>>(perm);

    turbo_persist<<<NB, 64>>>(perm);

    dim3 og(Kc / 32, Bc / 32);
    output_kernel<<<og, 256>>>(out);
}

// round 14
// speedup vs baseline: 1.3711x; 1.3711x over previous
#include <cuda_runtime.h>
#include <cuda_bf16.h>
#include <cuda_fp16.h>

// ---------------------------------------------------------------------------
// Turbo decoder (linear-domain BCJR in log2 units), 8-state RSC,
// B=256, K=6144, 6 iterations. Sliding-window (L=16, W=16) -> 384 chunks,
// 3072 two-warp blocks per pass. Branch metrics pre-combined:
// G[t][b] = (g0', g1') float2; passes write the next pass's G through the
// interleaver via SD = (ls'+lp', ls'-lp'). G rows for every walk segment are
// PRELOADED in register batches of 8 (MLP=8) so recursion steps carry no
// embedded L2 latency.
// ---------------------------------------------------------------------------

constexpr int Kc = 6144;
constexpr int Bc = 256;
constexpr int Lc = 16;
constexpr int Wc = 16;
constexpr int Cc = Kc / Lc;           // 384 chunks
constexpr int Hc = Lc / 2;            // 8
constexpr float SCALEF   = 0.7213475204444817f;   // 0.5*log2(e)
constexpr float OUTSCALE = -1.3862943611198906f;  // -2*ln2  (undo SCALEF, negate)
constexpr float GCLAMP   = 60.0f;                 // log2-unit branch clamp

// Static device scratch (no allocations anywhere).
__device__ float  g_ls1[Kc * Bc];
__device__ float  g_lp2[Kc * Bc];
__device__ float2 g_SD1[Kc * Bc];
__device__ float2 g_SD2[Kc * Bc];
__device__ float2 g_G1[Kc * Bc];
__device__ float2 g_G2[Kc * Bc];
__device__ float  g_lpost[Kc * Bc];
__device__ int    g_inv[Kc];

__device__ __forceinline__ float ex2f(float x) {
    float y; asm("ex2.approx.ftz.f32 %0, %1;" : "=f"(y) : "f"(x)); return y;
}
__device__ __forceinline__ float lg2f(float x) {
    float y; asm("lg2.approx.ftz.f32 %0, %1;" : "=f"(y) : "f"(x)); return y;
}

// r = 2^-(ilogb(s)) : exponent-field trick, no MUFU.
__device__ __forceinline__ float norm_scale(float s) {
    return __uint_as_float(0x7F000000u - (__float_as_uint(s) & 0x7F800000u));
}

__device__ __forceinline__ void weights(float2 g, float (&e)[4]) {
    e[0] = ex2f(g.x);  e[1] = ex2f(-g.x);
    e[2] = ex2f(g.y);  e[3] = ex2f(-g.y);
}

// Trellis (G0=(1,0,1,1), G1=(1,1,0,1), MU=3):
//   weight(s,u=0) = e0p for s in {0,1,6,7}, e1p for s in {2,3,4,5}; u=1 -> e*n.
//   next: 0:(0,4) 1:(4,0) 2:(5,1) 3:(1,5) 4:(2,6) 5:(6,2) 6:(7,3) 7:(3,7)

__device__ __forceinline__ void norm8(float (&v)[8]) {
    float s = ((v[0]+v[1])+(v[2]+v[3])) + ((v[4]+v[5])+(v[6]+v[7]));
    float r = norm_scale(s);
    #pragma unroll
    for (int i = 0; i < 8; ++i) v[i] *= r;
}

__device__ __forceinline__ void fwd_step(const float (&e)[4], float (&a)[8]) {
    float n0 = a[0]*e[0] + a[1]*e[1];
    float n4 = a[0]*e[1] + a[1]*e[0];
    float n5 = a[2]*e[2] + a[3]*e[3];
    float n1 = a[2]*e[3] + a[3]*e[2];
    float n2 = a[4]*e[2] + a[5]*e[3];
    float n6 = a[4]*e[3] + a[5]*e[2];
    float n7 = a[6]*e[0] + a[7]*e[1];
    float n3 = a[6]*e[1] + a[7]*e[0];
    a[0]=n0; a[1]=n1; a[2]=n2; a[3]=n3; a[4]=n4; a[5]=n5; a[6]=n6; a[7]=n7;
}

__device__ __forceinline__ void bwd_step(const float (&e)[4], float (&B)[8]) {
    float n0 = B[0]*e[0] + B[4]*e[1];
    float n1 = B[4]*e[0] + B[0]*e[1];
    float n2 = B[5]*e[2] + B[1]*e[3];
    float n3 = B[1]*e[2] + B[5]*e[3];
    float n4 = B[2]*e[2] + B[6]*e[3];
    float n5 = B[6]*e[2] + B[2]*e[3];
    float n6 = B[7]*e[0] + B[3]*e[1];
    float n7 = B[3]*e[0] + B[7]*e[1];
    B[0]=n0; B[1]=n1; B[2]=n2; B[3]=n3; B[4]=n4; B[5]=n5; B[6]=n6; B[7]=n7;
}

__device__ __forceinline__ uint4 pack8(const float (&v)[8]) {
    __half2 h01 = __floats2half2_rn(v[0], v[1]);
    __half2 h23 = __floats2half2_rn(v[2], v[3]);
    __half2 h45 = __floats2half2_rn(v[4], v[5]);
    __half2 h67 = __floats2half2_rn(v[6], v[7]);
    uint4 pk;
    pk.x = *reinterpret_cast<unsigned*>(&h01);
    pk.y = *reinterpret_cast<unsigned*>(&h23);
    pk.z = *reinterpret_cast<unsigned*>(&h45);
    pk.w = *reinterpret_cast<unsigned*>(&h67);
    return pk;
}

__device__ __forceinline__ void unpack8(uint4 pk, float (&v)[8]) {
    float2 q01 = __half22float2(*reinterpret_cast<__half2*>(&pk.x));
    float2 q23 = __half22float2(*reinterpret_cast<__half2*>(&pk.y));
    float2 q45 = __half22float2(*reinterpret_cast<__half2*>(&pk.z));
    float2 q67 = __half22float2(*reinterpret_cast<__half2*>(&pk.w));
    v[0]=q01.x; v[1]=q01.y; v[2]=q23.x; v[3]=q23.y;
    v[4]=q45.x; v[5]=q45.y; v[6]=q67.x; v[7]=q67.y;
}

__device__ __forceinline__ float posterior8(const float (&A)[8], const float (&v)[8],
                                            const float (&e)[4]) {
    float u0 = e[0] * (A[0]*v[0] + A[1]*v[4] + A[6]*v[7] + A[7]*v[3])
             + e[2] * (A[2]*v[5] + A[3]*v[1] + A[4]*v[2] + A[5]*v[6]);
    float u1 = e[1] * (A[0]*v[4] + A[1]*v[0] + A[6]*v[3] + A[7]*v[7])
             + e[3] * (A[2]*v[1] + A[3]*v[5] + A[4]*v[6] + A[5]*v[2]);
    return 0.5f * (lg2f(fmaxf(u0, 1e-30f)) - lg2f(fmaxf(u1, 1e-30f)));
}

// ---------------------------------------------------------------------------
// Setup kernels
// ---------------------------------------------------------------------------
__global__ void unpack_kernel(const float* __restrict__ in) {
    __shared__ float tile[3][32][33];
    int t0 = blockIdx.x * 32;
    int b0 = blockIdx.y * 32;
    int tid = threadIdx.x;
    for (int e = tid; e < 32 * 96; e += 256) {
        int db  = e / 96;
        int off = e % 96;
        float v = in[(size_t)(b0 + db) * (3 * Kc) + 3 * t0 + off];
        tile[off % 3][off / 3][db] = -SCALEF * v;
    }
    __syncthreads();
    for (int e = tid; e < 1024; e += 256) {
        int tt = e >> 5, bb = e & 31;
        int idx = (t0 + tt) * Bc + b0 + bb;
        float vls = tile[0][tt][bb];
        float vp1 = tile[1][tt][bb];
        float vp2 = tile[2][tt][bb];
        float s1 = vls + vp1, d1 = vls - vp1;
        g_ls1[idx] = vls;
        g_lp2[idx] = vp2;
        g_SD1[idx] = make_float2(s1, d1);
        g_G1[idx]  = make_float2(s1, d1);     // la = 0 for iteration 0
    }
}

__global__ void build_inv_kernel(const int* __restrict__ perm) {
    int j = blockIdx.x * 256 + threadIdx.x;
    if (j < Kc) g_inv[perm[j]] = j;
}

__global__ void gather2_kernel(const int* __restrict__ perm) {
    int b  = threadIdx.x;
    int j0 = blockIdx.x * 8;
    #pragma unroll
    for (int r = 0; r < 8; ++r) {
        int j = j0 + r;
        float vls = g_ls1[perm[j] * Bc + b];
        float vlp = g_lp2[j * Bc + b];
        g_SD2[j * Bc + b] = make_float2(vls + vlp, vls - vlp);
    }
}

// ---------------------------------------------------------------------------
// Fused balanced BCJR pass (L=16, W=16), register-batched G loads.
//   dec==0: reads G1, writes G2[inv[t]] from SD2 + extrinsic
//   dec==1: reads G2, writes G1[perm[t]] from SD1 + extrinsic
//   last!=0: also store lpost' (time-major).
// ---------------------------------------------------------------------------
__global__ void __launch_bounds__(64, 12) bcjr_pass(int dec, const int* __restrict__ perm, int last) {
    __shared__ uint4 sbeta[Lc][32];    // beta_{t+1} at slot t - t_lo  (8 KB)
    __shared__ uint4 salpha[Hc][32];   // alpha_t   at slot t - t_lo   (4 KB)

    const float2* __restrict__ G  = dec ? g_G2 : g_G1;
    float2* __restrict__ Gout     = dec ? g_G1 : g_G2;
    const float2* __restrict__ SD = dec ? g_SD1 : g_SD2;
    const int* __restrict__ map   = dec ? perm : g_inv;

    const int lane = threadIdx.x & 31;
    const int wid  = threadIdx.x >> 5;
    const int b    = blockIdx.y * 32 + lane;
    const int c    = blockIdx.x;
    const int t_lo = c * Lc;
    const int t_sh = t_lo + Lc - 1;

    if (wid == 0) {
        // ================= backward warp =================
        float B[8];
        #pragma unroll
        for (int s = 0; s < 8; ++s) B[s] = 0.125f;

        if (c != Cc - 1) {
            // warmup, exactly 16 steps (t_hi = t_sh + 16 <= Kc-1), batched 8+8
            const int t_hi = t_sh + Wc;
            float2 gw[8];
            #pragma unroll
            for (int j = 0; j < 8; ++j) gw[j] = G[(t_hi - j) * Bc + b];
            #pragma unroll
            for (int j = 0; j < 8; ++j) {
                float e[4]; weights(gw[j], e); bwd_step(e, B);
                if (j & 1) norm8(B);
            }
            #pragma unroll
            for (int j = 0; j < 8; ++j) gw[j] = G[(t_hi - 8 - j) * Bc + b];
            #pragma unroll
            for (int j = 0; j < 8; ++j) {
                float e[4]; weights(gw[j], e); bwd_step(e, B);
                if (j & 1) norm8(B);
            }
        }
        // upper half stores (slots 15..8), t = t_sh - j
        {
            float2 gu[8];
            #pragma unroll
            for (int j = 0; j < 8; ++j) gu[j] = G[(t_sh - j) * Bc + b];
            #pragma unroll
            for (int j = 0; j < 8; ++j) {
                sbeta[Lc - 1 - j][lane] = pack8(B);
                float e[4]; weights(gu[j], e); bwd_step(e, B); norm8(B);
            }
        }
        __syncthreads();
        // lower half stores (slots 7..0), t = t_lo + 7 - j; keep G batch for
        // the posterior loop below (reused, no reload).
        float2 gl[8];
        #pragma unroll
        for (int j = 0; j < 8; ++j) gl[j] = G[(t_lo + 7 - j) * Bc + b];
        #pragma unroll
        for (int j = 0; j < 8; ++j) {
            sbeta[7 - j][lane] = pack8(B);
            float e[4]; weights(gl[j], e); bwd_step(e, B); norm8(B);
        }
        // posteriors for the LOWER half; prefetch map rows + SD rows batched
        int rows[8];
        #pragma unroll
        for (int i = 0; i < 8; ++i) rows[i] = map[t_lo + i];
        float2 sd[8];
        #pragma unroll
        for (int i = 0; i < 8; ++i) sd[i] = SD[rows[i] * Bc + b];
        #pragma unroll
        for (int i = 0; i < 8; ++i) {
            float2 g = gl[7 - i];               // G row t_lo + i
            float A[8], v[8], e[4];
            unpack8(salpha[i][lane], A);
            unpack8(sbeta[i][lane], v);
            weights(g, e);
            float lps = posterior8(A, v, e);
            float ext = lps - 0.5f * (g.x + g.y);
            Gout[rows[i] * Bc + b] = make_float2(
                fminf(fmaxf(sd[i].x + ext, -GCLAMP), GCLAMP),
                fminf(fmaxf(sd[i].y + ext, -GCLAMP), GCLAMP));
            if (last) g_lpost[(t_lo + i) * Bc + b] = lps;
        }
    } else {
        // ================= forward warp =================
        float A[8];
        if (c == 0) {                         // exact init, no warmup
            #pragma unroll
            for (int s = 0; s < 8; ++s) A[s] = 0.0f;
            A[0] = 1.0f;
        } else {
            const int t0 = t_lo - Wc;         // >= 0 for c >= 1
            if (t0 == 0) {                    // c==1: warm from exact init
                A[0] = 1.0f;
                #pragma unroll
                for (int s = 1; s < 8; ++s) A[s] = 0.0f;
            } else {
                #pragma unroll
                for (int s = 0; s < 8; ++s) A[s] = 0.125f;
            }
            // warmup 16 steps, batched 8+8
            float2 gw[8];
            #pragma unroll
            for (int j = 0; j < 8; ++j) gw[j] = G[(t0 + j) * Bc + b];
            #pragma unroll
            for (int j = 0; j < 8; ++j) {
                float e[4]; weights(gw[j], e); fwd_step(e, A);
                if (j & 1) norm8(A);
            }
            #pragma unroll
            for (int j = 0; j < 8; ++j) gw[j] = G[(t0 + 8 + j) * Bc + b];
            #pragma unroll
            for (int j = 0; j < 8; ++j) {
                float e[4]; weights(gw[j], e); fwd_step(e, A);
                if (j & 1) norm8(A);
            }
        }
        // lower walk: store alpha_t, then step (batched G)
        {
            float2 gl[8];
            #pragma unroll
            for (int i = 0; i < 8; ++i) gl[i] = G[(t_lo + i) * Bc + b];
            #pragma unroll
            for (int i = 0; i < 8; ++i) {
                salpha[i][lane] = pack8(A);
                float e[4]; weights(gl[i], e); fwd_step(e, A); norm8(A);
            }
        }
        __syncthreads();
        // upper walk with inline posterior; batch G + map + SD prefetch
        {
            float2 gu[8];
            #pragma unroll
            for (int i = 0; i < 8; ++i) gu[i] = G[(t_lo + 8 + i) * Bc + b];
            int rows[8];
            #pragma unroll
            for (int i = 0; i < 8; ++i) rows[i] = map[t_lo + 8 + i];
            float2 sd[8];
            #pragma unroll
            for (int i = 0; i < 8; ++i) sd[i] = SD[rows[i] * Bc + b];
            #pragma unroll
            for (int i = 0; i < 8; ++i) {
                float e[4], v[8];
                weights(gu[i], e);
                unpack8(sbeta[8 + i][lane], v);
                float lps = posterior8(A, v, e);
                float ext = lps - 0.5f * (gu[i].x + gu[i].y);
                Gout[rows[i] * Bc + b] = make_float2(
                    fminf(fmaxf(sd[i].x + ext, -GCLAMP), GCLAMP),
                    fminf(fmaxf(sd[i].y + ext, -GCLAMP), GCLAMP));
                if (last) g_lpost[(t_lo + 8 + i) * Bc + b] = lps;
                fwd_step(e, A);
                norm8(A);
            }
        }
    }
}

// ---------------------------------------------------------------------------
// Output: out[b][i] = -2*ln2 * lpost'[inv[i]][b]
// ---------------------------------------------------------------------------
__global__ void output_kernel(float* __restrict__ out) {
    __shared__ float tile[32][33];
    int i0 = blockIdx.x * 32, b0 = blockIdx.y * 32;
    int tid = threadIdx.x;
    for (int e = tid; e < 1024; e += 256) {
        int ii = e >> 5, bb = e & 31;
        tile[ii][bb] = OUTSCALE * g_lpost[g_inv[i0 + ii] * Bc + b0 + bb];
    }
    __syncthreads();
    for (int e = tid; e < 1024; e += 256) {
        int bb = e >> 5, ii = e & 31;
        out[(size_t)(b0 + bb) * Kc + i0 + ii] = tile[ii][bb];
    }
}

// ---------------------------------------------------------------------------
extern "C" void kernel_launch(void* const* d_in, const int* in_sizes, int n_in,
                              void* d_out, int out_size) {
    const float* in  = (const float*)d_in[0];
    const int* perm  = (const int*)d_in[1];
    float* out       = (float*)d_out;

    dim3 upg(Kc / 32, Bc / 32);
    unpack_kernel<<<upg, 256>>>(in);
    build_inv_kernel<<<Kc / 256, 256>>>(perm);
    gather2_kernel<<<Kc / 8, 256>>>(perm);

    dim3 bg(Cc, Bc / 32);   // 384 x 8 blocks, 2 warps each -> 6144 warps
    for (int it = 0; it < 6; ++it) {
        bcjr_pass<<<bg, 64>>>(0, perm, 0);
        bcjr_pass<<<bg, 64>>>(1, perm, (it == 5) ? 1 : 0);
    }

    dim3 og(Kc / 32, Bc / 32);
    output_kernel<<<og, 256>>>(out);
}